// round 13
// baseline (speedup 1.0000x reference)
#include <cuda_runtime.h>
#include <cuda_fp16.h>
#include <math.h>
#include <stdint.h>

// Problem dims
#define NB   1024
#define LL   128
#define HH   512
#define OO   32000
#define H2   1024   // 2H
#define H3   1536   // 3H

#define HPAD 40     // smem row stride in halfs -> ldmatrix conflict-free

// ---------------- scratch (device globals; no allocation allowed) -----------
__device__ __align__(16) __half g_cat_h [NB * H2];
__device__ __align__(16) __half g_x_h   [NB * HH];
__device__ __align__(16) __half g_hid_h [NB * HH];
__device__ __align__(16) __half g_hnew_h[NB * HH];
__device__ __align__(16) __half g_logit_h[NB * OO];  // fp16 logits (65.5 MB)
__device__ __align__(16) float g_scr [NB * HH];      // comb split-K accumulator
__device__ __align__(16) float g_gx [NB * H3];
__device__ __align__(16) float g_gh [NB * H3];
__device__ __align__(16) float g_rowsum[NB];

// fp16 weight copies
__device__ __align__(16) __half g_attnW_h[LL * H2];
__device__ __align__(16) __half g_combW_h[HH * H2];
__device__ __align__(16) __half g_Wih_h  [H3 * HH];
__device__ __align__(16) __half g_Whh_h  [H3 * HH];
__device__ __align__(16) __half g_outW_h [OO * HH];

// ---------------- PTX helpers ------------------------------------------------
__device__ __forceinline__ uint32_t smem_u32(const void* p)
{
    return (uint32_t)__cvta_generic_to_shared(p);
}
__device__ __forceinline__ void cpasync16(uint32_t s, const void* g)
{
    asm volatile("cp.async.cg.shared.global [%0], [%1], 16;\n" :: "r"(s), "l"(g));
}
__device__ __forceinline__ void cp_commit() { asm volatile("cp.async.commit_group;\n"); }
__device__ __forceinline__ void cp_wait1()  { asm volatile("cp.async.wait_group 1;\n"); }

__device__ __forceinline__ void ldsm_x4(uint32_t* r, uint32_t addr)
{
    asm volatile("ldmatrix.sync.aligned.m8n8.x4.shared.b16 {%0,%1,%2,%3}, [%4];\n"
                 : "=r"(r[0]), "=r"(r[1]), "=r"(r[2]), "=r"(r[3]) : "r"(addr));
}
__device__ __forceinline__ void ldsm_x2(uint32_t* r, uint32_t addr)
{
    asm volatile("ldmatrix.sync.aligned.m8n8.x2.shared.b16 {%0,%1}, [%2];\n"
                 : "=r"(r[0]), "=r"(r[1]) : "r"(addr));
}
__device__ __forceinline__ void mma_f16(float* d, const uint32_t* a, const uint32_t* b)
{
    asm volatile(
        "mma.sync.aligned.m16n8k16.row.col.f32.f16.f16.f32 "
        "{%0,%1,%2,%3}, {%4,%5,%6,%7}, {%8,%9}, {%0,%1,%2,%3};\n"
        : "+f"(d[0]), "+f"(d[1]), "+f"(d[2]), "+f"(d[3])
        : "r"(a[0]), "r"(a[1]), "r"(a[2]), "r"(a[3]), "r"(b[0]), "r"(b[1]));
}

// =============================================================================
// fp16 HMMA GEMM (proven mainloop): BM=BN=128, BK=32, 256 thr, 64x32 warps.
// Split-K via blockIdx.z (koff = z*Ksub).
// mode 0: fp32 C+bias. mode 1: relu -> fp16 Ch.
// mode 2: fp16 logits -> Ch (+bias) + fp32 exp-sum into rowsum.
// mode 3: atomicAdd fp32 C, no bias.
// =============================================================================
#define HSTAGE (2 * 128 * HPAD)

__global__ __launch_bounds__(256, 2)
void k_gemm_f16(const __half* __restrict__ A, const __half* __restrict__ W,
                const float* __restrict__ bias,
                float* __restrict__ C, __half* __restrict__ Ch,
                float* __restrict__ rowsum,
                int Nd, int Kstride, int Ksub, int mode)
{
    extern __shared__ __half smh[];

    const int bm   = blockIdx.y * 128;
    const int bn   = blockIdx.x * 128;
    const int koff = blockIdx.z * Ksub;
    const int tid  = threadIdx.x;
    const int warp = tid >> 5;
    const int lane = tid & 31;
    const int gid  = lane >> 2;
    const int tig  = lane & 3;
    const int wm   = (warp >> 2) * 64;
    const int wn   = (warp & 3) * 32;

    const int arow = wm + (lane & 15);
    const int acol = (lane >> 4) * 8;
    const int brow = wn + (lane & 7);
    const int bcol = ((lane >> 3) & 1) * 8;

    const uint32_t smem_b = smem_u32(smh);

    float acc[4][4][4];
    #pragma unroll
    for (int i = 0; i < 4; i++)
        #pragma unroll
        for (int j = 0; j < 4; j++)
            #pragma unroll
            for (int r = 0; r < 4; r++) acc[i][j][r] = 0.f;

    const __half* Ag = A + (size_t)bm * Kstride + koff;
    const __half* Wg = W + (size_t)bn * Kstride + koff;
    const int nIter = Ksub >> 5;

    auto load_tiles = [&](int it, int stg) {
        const __half* a_src = Ag + it * 32;
        const __half* w_src = Wg + it * 32;
        uint32_t aBase = smem_b + (stg * HSTAGE) * 2u;
        uint32_t bBase = aBase + 128 * HPAD * 2u;
        #pragma unroll
        for (int j = 0; j < 2; j++) {
            int idx = tid + j * 256;
            int r = idx >> 2;
            int c = (idx & 3) * 8;
            cpasync16(aBase + (r * HPAD + c) * 2u, a_src + (size_t)r * Kstride + c);
        }
        #pragma unroll
        for (int j = 0; j < 2; j++) {
            int idx = tid + j * 256;
            int r = idx >> 2;
            int c = (idx & 3) * 8;
            cpasync16(bBase + (r * HPAD + c) * 2u, w_src + (size_t)r * Kstride + c);
        }
    };

    load_tiles(0, 0); cp_commit();
    load_tiles(1, 1); cp_commit();

    int stg = 0;
    for (int it = 0; it < nIter; ++it) {
        cp_wait1();
        __syncthreads();

        if (it + 2 < nIter) load_tiles(it + 2, (stg + 2) % 3);
        cp_commit();

        const uint32_t aBase = smem_b + (stg * HSTAGE) * 2u;
        const uint32_t bBase = aBase + 128 * HPAD * 2u;

        #pragma unroll
        for (int kk = 0; kk < 2; kk++) {
            uint32_t af[4][4], bf[4][2];
            #pragma unroll
            for (int mt = 0; mt < 4; mt++)
                ldsm_x4(af[mt], aBase + (((arow + mt * 16) * HPAD) + kk * 16 + acol) * 2u);
            #pragma unroll
            for (int nt = 0; nt < 4; nt++)
                ldsm_x2(bf[nt], bBase + (((brow + nt * 8) * HPAD) + kk * 16 + bcol) * 2u);
            #pragma unroll
            for (int mt = 0; mt < 4; mt++)
                #pragma unroll
                for (int nt = 0; nt < 4; nt++)
                    mma_f16(acc[mt][nt], af[mt], bf[nt]);
        }
        stg = (stg + 1) % 3;
    }

    #pragma unroll
    for (int mt = 0; mt < 4; mt++) {
        int r0 = bm + wm + mt * 16 + gid;
        float sum_lo = 0.f, sum_hi = 0.f;
        #pragma unroll
        for (int nt = 0; nt < 4; nt++) {
            int c0 = bn + wn + nt * 8 + tig * 2;
            if (mode == 3) {
                atomicAdd(&C[(size_t)(r0    ) * Nd + c0],     acc[mt][nt][0]);
                atomicAdd(&C[(size_t)(r0    ) * Nd + c0 + 1], acc[mt][nt][1]);
                atomicAdd(&C[(size_t)(r0 + 8) * Nd + c0],     acc[mt][nt][2]);
                atomicAdd(&C[(size_t)(r0 + 8) * Nd + c0 + 1], acc[mt][nt][3]);
                continue;
            }
            float b0v = bias[c0], b1v = bias[c0 + 1];
            float v0 = acc[mt][nt][0] + b0v;
            float v1 = acc[mt][nt][1] + b1v;
            float v2 = acc[mt][nt][2] + b0v;
            float v3 = acc[mt][nt][3] + b1v;
            if (mode == 1) {
                v0 = fmaxf(v0, 0.f); v1 = fmaxf(v1, 0.f);
                v2 = fmaxf(v2, 0.f); v3 = fmaxf(v3, 0.f);
                *(__half2*)&Ch[(size_t)(r0    ) * Nd + c0] = __floats2half2_rn(v0, v1);
                *(__half2*)&Ch[(size_t)(r0 + 8) * Nd + c0] = __floats2half2_rn(v2, v3);
            } else if (mode == 2) {
                sum_lo += __expf(v0) + __expf(v1);
                sum_hi += __expf(v2) + __expf(v3);
                *(__half2*)&Ch[(size_t)(r0    ) * Nd + c0] = __floats2half2_rn(v0, v1);
                *(__half2*)&Ch[(size_t)(r0 + 8) * Nd + c0] = __floats2half2_rn(v2, v3);
            } else {
                *(float2*)&C[(size_t)(r0    ) * Nd + c0] = make_float2(v0, v1);
                *(float2*)&C[(size_t)(r0 + 8) * Nd + c0] = make_float2(v2, v3);
            }
        }
        if (mode == 2) {
            sum_lo += __shfl_xor_sync(0xffffffff, sum_lo, 1);
            sum_lo += __shfl_xor_sync(0xffffffff, sum_lo, 2);
            sum_hi += __shfl_xor_sync(0xffffffff, sum_hi, 1);
            sum_hi += __shfl_xor_sync(0xffffffff, sum_hi, 2);
            if (tig == 0) {
                atomicAdd(&rowsum[r0],     sum_lo);
                atomicAdd(&rowsum[r0 + 8], sum_hi);
            }
        }
    }
}

// ---------------- fp32 -> fp16 conversion -------------------------------------
__device__ __forceinline__ void f2h_one(const float4* __restrict__ s,
                                        __half2* __restrict__ d, int i)
{
    float4 v = s[i];
    d[2 * i]     = __floats2half2_rn(v.x, v.y);
    d[2 * i + 1] = __floats2half2_rn(v.z, v.w);
}

__global__ void k_f2h(const float4* __restrict__ src, __half2* __restrict__ dst, int n4)
{
    int i = blockIdx.x * blockDim.x + threadIdx.x;
    if (i < n4) f2h_one(src, dst, i);
}

// merged homogeneous conversion of comb_W / W_ih / W_hh
__global__ void k_f2h3(const float4* __restrict__ combW,
                       const float4* __restrict__ Wih,
                       const float4* __restrict__ Whh)
{
    const int b = blockIdx.x;
    const int t = threadIdx.x;
    if (b < 512) {
        f2h_one(combW, (__half2*)g_combW_h, b * 256 + t);
    } else if (b < 1280) {
        f2h_one(Wih, (__half2*)g_Wih_h, (b - 512) * 256 + t);
    } else {
        f2h_one(Whh, (__half2*)g_Whh_h, (b - 1280) * 256 + t);
    }
}

// ---------------- zero all split-K accumulators + rowsum ----------------------
#define Z_ATTN  32768
#define Z_SCR   (Z_ATTN + 131072)
#define Z_GX    (Z_SCR + 393216)
#define Z_TOT   (Z_GX + 256)

__global__ void k_zero_all(float4* __restrict__ attn_w)
{
    int i = blockIdx.x * 256 + threadIdx.x;
    float4 z = make_float4(0.f, 0.f, 0.f, 0.f);
    if (i < Z_ATTN)      attn_w[i] = z;
    else if (i < Z_SCR)  ((float4*)g_scr)[i - Z_ATTN] = z;
    else if (i < Z_GX)   ((float4*)g_gx)[i - Z_SCR] = z;
    else if (i < Z_TOT)  ((float4*)g_rowsum)[i - Z_GX] = z;
}

// ---------------- K1: cat = [emb[id] | hidden] (fp16) + hidden fp16 ----------
__global__ void k_build_cat(const int* __restrict__ ids,
                            const float* __restrict__ hidden,
                            const float* __restrict__ emb)
{
    int n = blockIdx.x;
    int id = ids[n];
    int i = threadIdx.x;                  // 128 threads
    float4 e = ((const float4*)(emb    + (size_t)id * HH))[i];
    float4 h = ((const float4*)(hidden + (size_t)n  * HH))[i];

    __half2* c = (__half2*)(g_cat_h + (size_t)n * H2);
    c[2 * i]           = __floats2half2_rn(e.x, e.y);
    c[2 * i + 1]       = __floats2half2_rn(e.z, e.w);
    c[256 + 2 * i]     = __floats2half2_rn(h.x, h.y);
    c[256 + 2 * i + 1] = __floats2half2_rn(h.z, h.w);

    __half2* hh = (__half2*)(g_hid_h + (size_t)n * HH);
    hh[2 * i]     = __floats2half2_rn(h.x, h.y);
    hh[2 * i + 1] = __floats2half2_rn(h.z, h.w);
}

// ---------------- fused: softmax(logits + bias) + attn einsum ----------------
__global__ void k_attn_smax_apply(const float* __restrict__ eo,
                                  const float* __restrict__ mask,
                                  float* __restrict__ attn_w,
                                  const float* __restrict__ ab)
{
    __shared__ float red[128];
    __shared__ float ws[LL];
    int n = blockIdx.x;
    int t = threadIdx.x;                  // 128 threads

    float v = attn_w[(size_t)n * LL + t] + ab[t];

    red[t] = v; __syncthreads();
    for (int s = 64; s > 0; s >>= 1) {
        if (t < s) red[t] = fmaxf(red[t], red[t + s]);
        __syncthreads();
    }
    float m = red[0]; __syncthreads();

    float e = expf(v - m);
    red[t] = e; __syncthreads();
    for (int s = 64; s > 0; s >>= 1) {
        if (t < s) red[t] += red[t + s];
        __syncthreads();
    }
    float w = e / red[0];
    attn_w[(size_t)n * LL + t] = w;       // final attn weights (harness output)
    ws[t] = w;
    __syncthreads();

    const float4* e4 = (const float4*)(eo   + (size_t)n * LL * HH) + t;
    const float4* m4 = (const float4*)(mask + (size_t)n * LL * HH) + t;

    float4 acc = make_float4(0.f, 0.f, 0.f, 0.f);
    #pragma unroll 4
    for (int l = 0; l < LL; l++) {
        float4 e = e4[(size_t)l * 128];
        float4 m = m4[(size_t)l * 128];
        float  wv = ws[l];
        acc.x = fmaf(wv, e.x * m.x, acc.x);
        acc.y = fmaf(wv, e.y * m.y, acc.y);
        acc.z = fmaf(wv, e.z * m.z, acc.z);
        acc.w = fmaf(wv, e.w * m.w, acc.w);
    }
    __half2* dst = (__half2*)(g_cat_h + (size_t)n * H2 + HH);
    dst[2 * t]     = __floats2half2_rn(acc.x, acc.y);
    dst[2 * t + 1] = __floats2half2_rn(acc.z, acc.w);
}

// ---------------- relu(scr + comb_b) -> fp16 x --------------------------------
__global__ void k_relu_bias(const float* __restrict__ cb)
{
    int i = blockIdx.x * blockDim.x + threadIdx.x;    // over NB*HH/2
    int i2 = 2 * i;
    int c = i2 & (HH - 1);
    float v0 = fmaxf(g_scr[i2]     + cb[c],     0.f);
    float v1 = fmaxf(g_scr[i2 + 1] + cb[c + 1], 0.f);
    ((__half2*)g_x_h)[i] = __floats2half2_rn(v0, v1);
}

// ---------------- GRU gates (adds b_ih to gx) ---------------------------------
__global__ void k_gru(const float* __restrict__ hidden,
                      const float* __restrict__ b_ih,
                      float* __restrict__ h_new)
{
    int idx = blockIdx.x * blockDim.x + threadIdx.x;
    if (idx >= NB * HH) return;
    int n = idx >> 9;
    int h = idx & (HH - 1);
    size_t base = (size_t)n * H3 + h;

    float xr = g_gx[base]          + b_ih[h];
    float xz = g_gx[base + HH]     + b_ih[h + HH];
    float xn = g_gx[base + 2 * HH] + b_ih[h + 2 * HH];
    float hr = g_gh[base], hz = g_gh[base + HH], hn = g_gh[base + 2 * HH];

    float r = 1.f / (1.f + expf(-(xr + hr)));
    float z = 1.f / (1.f + expf(-(xz + hz)));
    float nn = tanhf(xn + r * hn);
    float hv = (1.f - z) * nn + z * hidden[idx];
    h_new[idx] = hv;
    g_hnew_h[idx] = __float2half_rn(hv);
}

// ---------------- out = fp16_logit - log(rowsum) (row range via pointers) ------
__global__ void k_sub_lse(float* __restrict__ x, const __half* __restrict__ lg,
                          const float* __restrict__ rs)
{
    int n = blockIdx.x;
    float lse = __logf(rs[n]);
    const uint2* src = (const uint2*)(lg + (size_t)n * OO);
    float4* dst = (float4*)(x + (size_t)n * OO);
    for (int i = threadIdx.x; i < OO / 4; i += blockDim.x) {
        uint2 u = src[i];
        float2 a = __half22float2(*(__half2*)&u.x);
        float2 b = __half22float2(*(__half2*)&u.y);
        dst[i] = make_float4(a.x - lse, a.y - lse, b.x - lse, b.y - lse);
    }
}

// ---------------- launch ---------------------------------------------------------
extern "C" void kernel_launch(void* const* d_in, const int* in_sizes, int n_in,
                              void* d_out, int out_size)
{
    const int*   ids     = (const int*)  d_in[0];
    const float* hidden  = (const float*)d_in[1];
    const float* eo      = (const float*)d_in[2];
    const float* mask    = (const float*)d_in[3];
    const float* emb     = (const float*)d_in[4];
    const float* attn_W  = (const float*)d_in[5];
    const float* attn_b  = (const float*)d_in[6];
    const float* comb_W  = (const float*)d_in[7];
    const float* comb_b  = (const float*)d_in[8];
    const float* W_ih    = (const float*)d_in[9];
    const float* W_hh    = (const float*)d_in[10];
    const float* b_ih    = (const float*)d_in[11];
    const float* b_hh    = (const float*)d_in[12];
    const float* out_W   = (const float*)d_in[13];
    const float* out_b   = (const float*)d_in[14];

    float* out    = (float*)d_out;                       // [N, O]
    float* h_new  = out + (size_t)NB * OO;               // [N, H]
    float* attn_w = h_new + (size_t)NB * HH;             // [N, L]

    float* gxp;   cudaGetSymbolAddress((void**)&gxp,  g_gx);
    float* ghp;   cudaGetSymbolAddress((void**)&ghp,  g_gh);
    float* rsp;   cudaGetSymbolAddress((void**)&rsp,  g_rowsum);
    float* scrp;  cudaGetSymbolAddress((void**)&scrp, g_scr);
    __half *catp, *xp, *hidp, *hnp, *logp, *aWp, *cWp, *ihp, *hhp, *oWp;
    cudaGetSymbolAddress((void**)&catp, g_cat_h);
    cudaGetSymbolAddress((void**)&xp,   g_x_h);
    cudaGetSymbolAddress((void**)&hidp, g_hid_h);
    cudaGetSymbolAddress((void**)&hnp,  g_hnew_h);
    cudaGetSymbolAddress((void**)&logp, g_logit_h);
    cudaGetSymbolAddress((void**)&aWp,  g_attnW_h);
    cudaGetSymbolAddress((void**)&cWp,  g_combW_h);
    cudaGetSymbolAddress((void**)&ihp,  g_Wih_h);
    cudaGetSymbolAddress((void**)&hhp,  g_Whh_h);
    cudaGetSymbolAddress((void**)&oWp,  g_outW_h);

    const int SMEM = 3 * HSTAGE * sizeof(__half);        // 61440 B
    cudaFuncSetAttribute(k_gemm_f16, cudaFuncAttributeMaxDynamicSharedMemorySize, SMEM);

    // one-time side stream + fork/join events (host resources only)
    static cudaStream_t s2 = nullptr;
    static cudaEvent_t  e0 = nullptr, e1 = nullptr, eW = nullptr, eC = nullptr,
                        eG = nullptr, e3 = nullptr, eA = nullptr, eB = nullptr,
                        eL = nullptr;
    if (!s2) {
        cudaStreamCreateWithFlags(&s2, cudaStreamNonBlocking);
        cudaEventCreateWithFlags(&e0, cudaEventDisableTiming);
        cudaEventCreateWithFlags(&e1, cudaEventDisableTiming);
        cudaEventCreateWithFlags(&eW, cudaEventDisableTiming);
        cudaEventCreateWithFlags(&eC, cudaEventDisableTiming);
        cudaEventCreateWithFlags(&eG, cudaEventDisableTiming);
        cudaEventCreateWithFlags(&e3, cudaEventDisableTiming);
        cudaEventCreateWithFlags(&eA, cudaEventDisableTiming);
        cudaEventCreateWithFlags(&eB, cudaEventDisableTiming);
        cudaEventCreateWithFlags(&eL, cudaEventDisableTiming);
    }

    // ---- fork ------------------------------------------------------------------
    cudaEventRecord(e0, 0);
    cudaStreamWaitEvent(s2, e0, 0);

    // main: build cat (hidden fp16 feeds gh on side stream)
    k_build_cat<<<NB, 128>>>(ids, hidden, emb);
    cudaEventRecord(eC, 0);

    // side: zero split-K accumulators + rowsum, then attn_W fp16
    k_zero_all<<<(Z_TOT + 255) / 256, 256, 0, s2>>>((float4*)attn_w);
    k_f2h<<<LL * H2 / 4 / 256, 256, 0, s2>>>((const float4*)attn_W,
                                             (__half2*)aWp, LL * H2 / 4);
    cudaEventRecord(e1, s2);
    // side: comb/ih/hh fp16
    k_f2h3<<<2048, 256, 0, s2>>>((const float4*)comb_W, (const float4*)W_ih,
                                 (const float4*)W_hh);
    cudaEventRecord(eW, s2);
    // side: gh = hidden @ W_hh^T + b_hh  (compute, overlaps DRAM-bound attn)
    cudaStreamWaitEvent(s2, eC, 0);
    {
        dim3 grid(H3 / 128, NB / 128, 1);
        k_gemm_f16<<<grid, 256, SMEM, s2>>>(hidp, hhp, b_hh, ghp, nullptr, nullptr,
                                            H3, HH, HH, 0);
    }
    cudaEventRecord(eG, s2);
    // side: out_W fp16 (only needed by big GEMM)
    k_f2h<<<(OO * HH / 4) / 256, 256, 0, s2>>>((const float4*)out_W,
                                               (__half2*)oWp, OO * HH / 4);
    cudaEventRecord(e3, s2);

    // ---- main chain --------------------------------------------------------------
    cudaStreamWaitEvent(0, e1, 0);
    // 2. attn logits, split-K=4, atomic (bias folded into fused softmax)
    {
        dim3 grid(LL / 128, NB / 128, 4);
        k_gemm_f16<<<grid, 256, SMEM>>>(catp, aWp, nullptr, attn_w, nullptr, nullptr,
                                        LL, H2, H2 / 4, 3);
    }
    // 3+4. fused softmax + attn_applied
    k_attn_smax_apply<<<NB, 128>>>(eo, mask, attn_w, attn_b);

    cudaStreamWaitEvent(0, eW, 0);
    // 5. comb split-K=4 atomic -> scr, then relu+bias -> fp16 x
    {
        dim3 grid(HH / 128, NB / 128, 4);
        k_gemm_f16<<<grid, 256, SMEM>>>(catp, cWp, nullptr, scrp, nullptr, nullptr,
                                        HH, H2, H2 / 4, 3);
    }
    k_relu_bias<<<NB * HH / 2 / 256, 256>>>(comb_b);
    // 6. gx split-K=2 atomic (b_ih added in k_gru)
    {
        dim3 grid(H3 / 128, NB / 128, 2);
        k_gemm_f16<<<grid, 256, SMEM>>>(xp, ihp, nullptr, gxp, nullptr, nullptr,
                                        H3, HH, HH / 2, 3);
    }
    cudaStreamWaitEvent(0, eG, 0);                 // gh done (side stream)
    // 8. GRU gates -> h_new
    k_gru<<<(NB * HH + 255) / 256, 256>>>(hidden, b_ih, h_new);

    cudaStreamWaitEvent(0, e3, 0);                 // out_W fp16 ready
    // 9a. big GEMM strip A: rows [0, 896)  (1750 CTAs ~ 5.91 waves)
    {
        dim3 grid(OO / 128, 7, 1);
        k_gemm_f16<<<grid, 256, SMEM>>>(hnp, oWp, out_b, nullptr, logp, rsp,
                                        OO, HH, HH, 2);
    }
    cudaEventRecord(eA, 0);
    // 9b. big GEMM strip B: rows [896, 1024)  (250 CTAs, ~1 wave)
    {
        dim3 grid(OO / 128, 1, 1);
        k_gemm_f16<<<grid, 256, SMEM>>>(hnp + (size_t)896 * HH, oWp, out_b,
                                        nullptr, logp + (size_t)896 * OO,
                                        rsp + 896, OO, HH, HH, 2);
    }
    cudaEventRecord(eB, 0);

    // side: sub_lse strip A overlaps GEMM strip B
    cudaStreamWaitEvent(s2, eA, 0);
    k_sub_lse<<<896, 256, 0, s2>>>(out, logp, rsp);
    cudaStreamWaitEvent(s2, eB, 0);
    k_sub_lse<<<128, 256, 0, s2>>>(out + (size_t)896 * OO,
                                   logp + (size_t)896 * OO, rsp + 896);
    cudaEventRecord(eL, s2);

    // join: everything visible on the capture-origin stream
    cudaStreamWaitEvent(0, eL, 0);
}

// round 14
// speedup vs baseline: 1.0051x; 1.0051x over previous
#include <cuda_runtime.h>
#include <cuda_fp16.h>
#include <math.h>
#include <stdint.h>

// Problem dims
#define NB   1024
#define LL   128
#define HH   512
#define OO   32000
#define H2   1024   // 2H
#define H3   1536   // 3H

#define HPAD 40     // smem row stride in halfs -> ldmatrix conflict-free

// ---------------- scratch (device globals; no allocation allowed) -----------
__device__ __align__(16) __half g_cat_h [NB * H2];
__device__ __align__(16) __half g_x_h   [NB * HH];
__device__ __align__(16) __half g_hid_h [NB * HH];
__device__ __align__(16) __half g_hnew_h[NB * HH];
__device__ __align__(16) __half g_logit_h[NB * OO];  // fp16 logits (65.5 MB)
__device__ __align__(16) float g_scr [NB * HH];      // comb split-K accumulator
__device__ __align__(16) float g_gx [NB * H3];
__device__ __align__(16) float g_gh [NB * H3];
__device__ __align__(16) float g_rowsum[NB];

// fp16 weight copies
__device__ __align__(16) __half g_attnW_h[LL * H2];
__device__ __align__(16) __half g_combW_h[HH * H2];
__device__ __align__(16) __half g_Wih_h  [H3 * HH];
__device__ __align__(16) __half g_Whh_h  [H3 * HH];
__device__ __align__(16) __half g_outW_h [OO * HH];

// ---------------- PTX helpers ------------------------------------------------
__device__ __forceinline__ uint32_t smem_u32(const void* p)
{
    return (uint32_t)__cvta_generic_to_shared(p);
}
__device__ __forceinline__ void cpasync16(uint32_t s, const void* g)
{
    asm volatile("cp.async.cg.shared.global [%0], [%1], 16;\n" :: "r"(s), "l"(g));
}
__device__ __forceinline__ void cp_commit() { asm volatile("cp.async.commit_group;\n"); }
__device__ __forceinline__ void cp_wait1()  { asm volatile("cp.async.wait_group 1;\n"); }

__device__ __forceinline__ void ldsm_x4(uint32_t* r, uint32_t addr)
{
    asm volatile("ldmatrix.sync.aligned.m8n8.x4.shared.b16 {%0,%1,%2,%3}, [%4];\n"
                 : "=r"(r[0]), "=r"(r[1]), "=r"(r[2]), "=r"(r[3]) : "r"(addr));
}
__device__ __forceinline__ void ldsm_x2(uint32_t* r, uint32_t addr)
{
    asm volatile("ldmatrix.sync.aligned.m8n8.x2.shared.b16 {%0,%1}, [%2];\n"
                 : "=r"(r[0]), "=r"(r[1]) : "r"(addr));
}
__device__ __forceinline__ void mma_f16(float* d, const uint32_t* a, const uint32_t* b)
{
    asm volatile(
        "mma.sync.aligned.m16n8k16.row.col.f32.f16.f16.f32 "
        "{%0,%1,%2,%3}, {%4,%5,%6,%7}, {%8,%9}, {%0,%1,%2,%3};\n"
        : "+f"(d[0]), "+f"(d[1]), "+f"(d[2]), "+f"(d[3])
        : "r"(a[0]), "r"(a[1]), "r"(a[2]), "r"(a[3]), "r"(b[0]), "r"(b[1]));
}
// fp16-accumulate variant: d/c are 2 b32 regs (4 halves), same lane->element map
__device__ __forceinline__ void mma_f16acc(uint32_t* d, const uint32_t* a, const uint32_t* b)
{
    asm volatile(
        "mma.sync.aligned.m16n8k16.row.col.f16.f16.f16.f16 "
        "{%0,%1}, {%2,%3,%4,%5}, {%6,%7}, {%0,%1};\n"
        : "+r"(d[0]), "+r"(d[1])
        : "r"(a[0]), "r"(a[1]), "r"(a[2]), "r"(a[3]), "r"(b[0]), "r"(b[1]));
}

// =============================================================================
// fp16 HMMA GEMM (proven mainloop): BM=BN=128, BK=32, 256 thr, 64x32 warps.
// Split-K via blockIdx.z (koff = z*Ksub).
// mode 0: fp32 C+bias. mode 1: relu -> fp16 Ch.
// mode 2: fp16 logits -> Ch (+bias) + fp32 exp-sum into rowsum.
// mode 3: atomicAdd fp32 C, no bias.
// =============================================================================
#define HSTAGE (2 * 128 * HPAD)

__global__ __launch_bounds__(256, 2)
void k_gemm_f16(const __half* __restrict__ A, const __half* __restrict__ W,
                const float* __restrict__ bias,
                float* __restrict__ C, __half* __restrict__ Ch,
                float* __restrict__ rowsum,
                int Nd, int Kstride, int Ksub, int mode)
{
    extern __shared__ __half smh[];

    const int bm   = blockIdx.y * 128;
    const int bn   = blockIdx.x * 128;
    const int koff = blockIdx.z * Ksub;
    const int tid  = threadIdx.x;
    const int warp = tid >> 5;
    const int lane = tid & 31;
    const int gid  = lane >> 2;
    const int tig  = lane & 3;
    const int wm   = (warp >> 2) * 64;
    const int wn   = (warp & 3) * 32;

    const int arow = wm + (lane & 15);
    const int acol = (lane >> 4) * 8;
    const int brow = wn + (lane & 7);
    const int bcol = ((lane >> 3) & 1) * 8;

    const uint32_t smem_b = smem_u32(smh);

    float acc[4][4][4];
    #pragma unroll
    for (int i = 0; i < 4; i++)
        #pragma unroll
        for (int j = 0; j < 4; j++)
            #pragma unroll
            for (int r = 0; r < 4; r++) acc[i][j][r] = 0.f;

    const __half* Ag = A + (size_t)bm * Kstride + koff;
    const __half* Wg = W + (size_t)bn * Kstride + koff;
    const int nIter = Ksub >> 5;

    auto load_tiles = [&](int it, int stg) {
        const __half* a_src = Ag + it * 32;
        const __half* w_src = Wg + it * 32;
        uint32_t aBase = smem_b + (stg * HSTAGE) * 2u;
        uint32_t bBase = aBase + 128 * HPAD * 2u;
        #pragma unroll
        for (int j = 0; j < 2; j++) {
            int idx = tid + j * 256;
            int r = idx >> 2;
            int c = (idx & 3) * 8;
            cpasync16(aBase + (r * HPAD + c) * 2u, a_src + (size_t)r * Kstride + c);
        }
        #pragma unroll
        for (int j = 0; j < 2; j++) {
            int idx = tid + j * 256;
            int r = idx >> 2;
            int c = (idx & 3) * 8;
            cpasync16(bBase + (r * HPAD + c) * 2u, w_src + (size_t)r * Kstride + c);
        }
    };

    load_tiles(0, 0); cp_commit();
    load_tiles(1, 1); cp_commit();

    int stg = 0;
    for (int it = 0; it < nIter; ++it) {
        cp_wait1();
        __syncthreads();

        if (it + 2 < nIter) load_tiles(it + 2, (stg + 2) % 3);
        cp_commit();

        const uint32_t aBase = smem_b + (stg * HSTAGE) * 2u;
        const uint32_t bBase = aBase + 128 * HPAD * 2u;

        #pragma unroll
        for (int kk = 0; kk < 2; kk++) {
            uint32_t af[4][4], bf[4][2];
            #pragma unroll
            for (int mt = 0; mt < 4; mt++)
                ldsm_x4(af[mt], aBase + (((arow + mt * 16) * HPAD) + kk * 16 + acol) * 2u);
            #pragma unroll
            for (int nt = 0; nt < 4; nt++)
                ldsm_x2(bf[nt], bBase + (((brow + nt * 8) * HPAD) + kk * 16 + bcol) * 2u);
            #pragma unroll
            for (int mt = 0; mt < 4; mt++)
                #pragma unroll
                for (int nt = 0; nt < 4; nt++)
                    mma_f16(acc[mt][nt], af[mt], bf[nt]);
        }
        stg = (stg + 1) % 3;
    }

    #pragma unroll
    for (int mt = 0; mt < 4; mt++) {
        int r0 = bm + wm + mt * 16 + gid;
        float sum_lo = 0.f, sum_hi = 0.f;
        #pragma unroll
        for (int nt = 0; nt < 4; nt++) {
            int c0 = bn + wn + nt * 8 + tig * 2;
            if (mode == 3) {
                atomicAdd(&C[(size_t)(r0    ) * Nd + c0],     acc[mt][nt][0]);
                atomicAdd(&C[(size_t)(r0    ) * Nd + c0 + 1], acc[mt][nt][1]);
                atomicAdd(&C[(size_t)(r0 + 8) * Nd + c0],     acc[mt][nt][2]);
                atomicAdd(&C[(size_t)(r0 + 8) * Nd + c0 + 1], acc[mt][nt][3]);
                continue;
            }
            float b0v = bias[c0], b1v = bias[c0 + 1];
            float v0 = acc[mt][nt][0] + b0v;
            float v1 = acc[mt][nt][1] + b1v;
            float v2 = acc[mt][nt][2] + b0v;
            float v3 = acc[mt][nt][3] + b1v;
            if (mode == 1) {
                v0 = fmaxf(v0, 0.f); v1 = fmaxf(v1, 0.f);
                v2 = fmaxf(v2, 0.f); v3 = fmaxf(v3, 0.f);
                *(__half2*)&Ch[(size_t)(r0    ) * Nd + c0] = __floats2half2_rn(v0, v1);
                *(__half2*)&Ch[(size_t)(r0 + 8) * Nd + c0] = __floats2half2_rn(v2, v3);
            } else if (mode == 2) {
                sum_lo += __expf(v0) + __expf(v1);
                sum_hi += __expf(v2) + __expf(v3);
                *(__half2*)&Ch[(size_t)(r0    ) * Nd + c0] = __floats2half2_rn(v0, v1);
                *(__half2*)&Ch[(size_t)(r0 + 8) * Nd + c0] = __floats2half2_rn(v2, v3);
            } else {
                *(float2*)&C[(size_t)(r0    ) * Nd + c0] = make_float2(v0, v1);
                *(float2*)&C[(size_t)(r0 + 8) * Nd + c0] = make_float2(v2, v3);
            }
        }
        if (mode == 2) {
            sum_lo += __shfl_xor_sync(0xffffffff, sum_lo, 1);
            sum_lo += __shfl_xor_sync(0xffffffff, sum_lo, 2);
            sum_hi += __shfl_xor_sync(0xffffffff, sum_hi, 1);
            sum_hi += __shfl_xor_sync(0xffffffff, sum_hi, 2);
            if (tig == 0) {
                atomicAdd(&rowsum[r0],     sum_lo);
                atomicAdd(&rowsum[r0 + 8], sum_hi);
            }
        }
    }
}

// =============================================================================
// Big output GEMM with fp16 ACCUMULATORS (rate experiment).
// Same tiling/pipeline; acc = 2 b32 regs per tile. Epilogue: fp32 convert,
// bias, exp-sum, fp16 logit store.
// =============================================================================
__global__ __launch_bounds__(256, 2)
void k_out_h(const __half* __restrict__ A, const __half* __restrict__ W,
             const float* __restrict__ bias, __half* __restrict__ Ch,
             float* __restrict__ rowsum)
{
    extern __shared__ __half smh[];

    const int bm   = blockIdx.y * 128;
    const int bn   = blockIdx.x * 128;
    const int tid  = threadIdx.x;
    const int warp = tid >> 5;
    const int lane = tid & 31;
    const int gid  = lane >> 2;
    const int tig  = lane & 3;
    const int wm   = (warp >> 2) * 64;
    const int wn   = (warp & 3) * 32;

    const int arow = wm + (lane & 15);
    const int acol = (lane >> 4) * 8;
    const int brow = wn + (lane & 7);
    const int bcol = ((lane >> 3) & 1) * 8;

    const uint32_t smem_b = smem_u32(smh);

    uint32_t acch[4][4][2];
    #pragma unroll
    for (int i = 0; i < 4; i++)
        #pragma unroll
        for (int j = 0; j < 4; j++) { acch[i][j][0] = 0u; acch[i][j][1] = 0u; }

    const __half* Ag = A + (size_t)bm * HH;
    const __half* Wg = W + (size_t)bn * HH;
    const int nIter = HH >> 5;    // 16

    auto load_tiles = [&](int it, int stg) {
        const __half* a_src = Ag + it * 32;
        const __half* w_src = Wg + it * 32;
        uint32_t aBase = smem_b + (stg * HSTAGE) * 2u;
        uint32_t bBase = aBase + 128 * HPAD * 2u;
        #pragma unroll
        for (int j = 0; j < 2; j++) {
            int idx = tid + j * 256;
            int r = idx >> 2;
            int c = (idx & 3) * 8;
            cpasync16(aBase + (r * HPAD + c) * 2u, a_src + (size_t)r * HH + c);
        }
        #pragma unroll
        for (int j = 0; j < 2; j++) {
            int idx = tid + j * 256;
            int r = idx >> 2;
            int c = (idx & 3) * 8;
            cpasync16(bBase + (r * HPAD + c) * 2u, w_src + (size_t)r * HH + c);
        }
    };

    load_tiles(0, 0); cp_commit();
    load_tiles(1, 1); cp_commit();

    int stg = 0;
    for (int it = 0; it < nIter; ++it) {
        cp_wait1();
        __syncthreads();

        if (it + 2 < nIter) load_tiles(it + 2, (stg + 2) % 3);
        cp_commit();

        const uint32_t aBase = smem_b + (stg * HSTAGE) * 2u;
        const uint32_t bBase = aBase + 128 * HPAD * 2u;

        #pragma unroll
        for (int kk = 0; kk < 2; kk++) {
            uint32_t af[4][4], bf[4][2];
            #pragma unroll
            for (int mt = 0; mt < 4; mt++)
                ldsm_x4(af[mt], aBase + (((arow + mt * 16) * HPAD) + kk * 16 + acol) * 2u);
            #pragma unroll
            for (int nt = 0; nt < 4; nt++)
                ldsm_x2(bf[nt], bBase + (((brow + nt * 8) * HPAD) + kk * 16 + bcol) * 2u);
            #pragma unroll
            for (int mt = 0; mt < 4; mt++)
                #pragma unroll
                for (int nt = 0; nt < 4; nt++)
                    mma_f16acc(acch[mt][nt], af[mt], bf[nt]);
        }
        stg = (stg + 1) % 3;
    }

    // epilogue: fp32 convert + bias + exp-sum + fp16 logit store
    #pragma unroll
    for (int mt = 0; mt < 4; mt++) {
        int r0 = bm + wm + mt * 16 + gid;
        float sum_lo = 0.f, sum_hi = 0.f;
        #pragma unroll
        for (int nt = 0; nt < 4; nt++) {
            int c0 = bn + wn + nt * 8 + tig * 2;
            float2 lo = __half22float2(*(__half2*)&acch[mt][nt][0]);
            float2 hi = __half22float2(*(__half2*)&acch[mt][nt][1]);
            float b0v = bias[c0], b1v = bias[c0 + 1];
            float v0 = lo.x + b0v;
            float v1 = lo.y + b1v;
            float v2 = hi.x + b0v;
            float v3 = hi.y + b1v;
            sum_lo += __expf(v0) + __expf(v1);
            sum_hi += __expf(v2) + __expf(v3);
            *(__half2*)&Ch[(size_t)(r0    ) * OO + c0] = __floats2half2_rn(v0, v1);
            *(__half2*)&Ch[(size_t)(r0 + 8) * OO + c0] = __floats2half2_rn(v2, v3);
        }
        sum_lo += __shfl_xor_sync(0xffffffff, sum_lo, 1);
        sum_lo += __shfl_xor_sync(0xffffffff, sum_lo, 2);
        sum_hi += __shfl_xor_sync(0xffffffff, sum_hi, 1);
        sum_hi += __shfl_xor_sync(0xffffffff, sum_hi, 2);
        if (tig == 0) {
            atomicAdd(&rowsum[r0],     sum_lo);
            atomicAdd(&rowsum[r0 + 8], sum_hi);
        }
    }
}

// ---------------- fp32 -> fp16 conversion -------------------------------------
__device__ __forceinline__ void f2h_one(const float4* __restrict__ s,
                                        __half2* __restrict__ d, int i)
{
    float4 v = s[i];
    d[2 * i]     = __floats2half2_rn(v.x, v.y);
    d[2 * i + 1] = __floats2half2_rn(v.z, v.w);
}

__global__ void k_f2h(const float4* __restrict__ src, __half2* __restrict__ dst, int n4)
{
    int i = blockIdx.x * blockDim.x + threadIdx.x;
    if (i < n4) f2h_one(src, dst, i);
}

__global__ void k_f2h3(const float4* __restrict__ combW,
                       const float4* __restrict__ Wih,
                       const float4* __restrict__ Whh)
{
    const int b = blockIdx.x;
    const int t = threadIdx.x;
    if (b < 512) {
        f2h_one(combW, (__half2*)g_combW_h, b * 256 + t);
    } else if (b < 1280) {
        f2h_one(Wih, (__half2*)g_Wih_h, (b - 512) * 256 + t);
    } else {
        f2h_one(Whh, (__half2*)g_Whh_h, (b - 1280) * 256 + t);
    }
}

// ---------------- zero all split-K accumulators + rowsum ----------------------
#define Z_ATTN  32768
#define Z_SCR   (Z_ATTN + 131072)
#define Z_GX    (Z_SCR + 393216)
#define Z_TOT   (Z_GX + 256)

__global__ void k_zero_all(float4* __restrict__ attn_w)
{
    int i = blockIdx.x * 256 + threadIdx.x;
    float4 z = make_float4(0.f, 0.f, 0.f, 0.f);
    if (i < Z_ATTN)      attn_w[i] = z;
    else if (i < Z_SCR)  ((float4*)g_scr)[i - Z_ATTN] = z;
    else if (i < Z_GX)   ((float4*)g_gx)[i - Z_SCR] = z;
    else if (i < Z_TOT)  ((float4*)g_rowsum)[i - Z_GX] = z;
}

// ---------------- K1: cat = [emb[id] | hidden] (fp16) + hidden fp16 ----------
__global__ void k_build_cat(const int* __restrict__ ids,
                            const float* __restrict__ hidden,
                            const float* __restrict__ emb)
{
    int n = blockIdx.x;
    int id = ids[n];
    int i = threadIdx.x;                  // 128 threads
    float4 e = ((const float4*)(emb    + (size_t)id * HH))[i];
    float4 h = ((const float4*)(hidden + (size_t)n  * HH))[i];

    __half2* c = (__half2*)(g_cat_h + (size_t)n * H2);
    c[2 * i]           = __floats2half2_rn(e.x, e.y);
    c[2 * i + 1]       = __floats2half2_rn(e.z, e.w);
    c[256 + 2 * i]     = __floats2half2_rn(h.x, h.y);
    c[256 + 2 * i + 1] = __floats2half2_rn(h.z, h.w);

    __half2* hh = (__half2*)(g_hid_h + (size_t)n * HH);
    hh[2 * i]     = __floats2half2_rn(h.x, h.y);
    hh[2 * i + 1] = __floats2half2_rn(h.z, h.w);
}

// ---------------- fused: softmax(logits + bias) + attn einsum ----------------
__global__ void k_attn_smax_apply(const float* __restrict__ eo,
                                  const float* __restrict__ mask,
                                  float* __restrict__ attn_w,
                                  const float* __restrict__ ab)
{
    __shared__ float red[128];
    __shared__ float ws[LL];
    int n = blockIdx.x;
    int t = threadIdx.x;                  // 128 threads

    float v = attn_w[(size_t)n * LL + t] + ab[t];

    red[t] = v; __syncthreads();
    for (int s = 64; s > 0; s >>= 1) {
        if (t < s) red[t] = fmaxf(red[t], red[t + s]);
        __syncthreads();
    }
    float m = red[0]; __syncthreads();

    float e = expf(v - m);
    red[t] = e; __syncthreads();
    for (int s = 64; s > 0; s >>= 1) {
        if (t < s) red[t] += red[t + s];
        __syncthreads();
    }
    float w = e / red[0];
    attn_w[(size_t)n * LL + t] = w;       // final attn weights (harness output)
    ws[t] = w;
    __syncthreads();

    const float4* e4 = (const float4*)(eo   + (size_t)n * LL * HH) + t;
    const float4* m4 = (const float4*)(mask + (size_t)n * LL * HH) + t;

    float4 acc = make_float4(0.f, 0.f, 0.f, 0.f);
    #pragma unroll 4
    for (int l = 0; l < LL; l++) {
        float4 e = e4[(size_t)l * 128];
        float4 m = m4[(size_t)l * 128];
        float  wv = ws[l];
        acc.x = fmaf(wv, e.x * m.x, acc.x);
        acc.y = fmaf(wv, e.y * m.y, acc.y);
        acc.z = fmaf(wv, e.z * m.z, acc.z);
        acc.w = fmaf(wv, e.w * m.w, acc.w);
    }
    __half2* dst = (__half2*)(g_cat_h + (size_t)n * H2 + HH);
    dst[2 * t]     = __floats2half2_rn(acc.x, acc.y);
    dst[2 * t + 1] = __floats2half2_rn(acc.z, acc.w);
}

// ---------------- relu(scr + comb_b) -> fp16 x --------------------------------
__global__ void k_relu_bias(const float* __restrict__ cb)
{
    int i = blockIdx.x * blockDim.x + threadIdx.x;    // over NB*HH/2
    int i2 = 2 * i;
    int c = i2 & (HH - 1);
    float v0 = fmaxf(g_scr[i2]     + cb[c],     0.f);
    float v1 = fmaxf(g_scr[i2 + 1] + cb[c + 1], 0.f);
    ((__half2*)g_x_h)[i] = __floats2half2_rn(v0, v1);
}

// ---------------- GRU gates (adds b_ih to gx) ---------------------------------
__global__ void k_gru(const float* __restrict__ hidden,
                      const float* __restrict__ b_ih,
                      float* __restrict__ h_new)
{
    int idx = blockIdx.x * blockDim.x + threadIdx.x;
    if (idx >= NB * HH) return;
    int n = idx >> 9;
    int h = idx & (HH - 1);
    size_t base = (size_t)n * H3 + h;

    float xr = g_gx[base]          + b_ih[h];
    float xz = g_gx[base + HH]     + b_ih[h + HH];
    float xn = g_gx[base + 2 * HH] + b_ih[h + 2 * HH];
    float hr = g_gh[base], hz = g_gh[base + HH], hn = g_gh[base + 2 * HH];

    float r = 1.f / (1.f + expf(-(xr + hr)));
    float z = 1.f / (1.f + expf(-(xz + hz)));
    float nn = tanhf(xn + r * hn);
    float hv = (1.f - z) * nn + z * hidden[idx];
    h_new[idx] = hv;
    g_hnew_h[idx] = __float2half_rn(hv);
}

// ---------------- out = fp16_logit - log(rowsum) (fp32 write) ------------------
__global__ void k_sub_lse(float* __restrict__ x)
{
    int n = blockIdx.x;
    float lse = __logf(g_rowsum[n]);
    const uint2* src = (const uint2*)(g_logit_h + (size_t)n * OO);
    float4* dst = (float4*)(x + (size_t)n * OO);
    for (int i = threadIdx.x; i < OO / 4; i += blockDim.x) {
        uint2 u = src[i];
        float2 a = __half22float2(*(__half2*)&u.x);
        float2 b = __half22float2(*(__half2*)&u.y);
        dst[i] = make_float4(a.x - lse, a.y - lse, b.x - lse, b.y - lse);
    }
}

// ---------------- launch ---------------------------------------------------------
extern "C" void kernel_launch(void* const* d_in, const int* in_sizes, int n_in,
                              void* d_out, int out_size)
{
    const int*   ids     = (const int*)  d_in[0];
    const float* hidden  = (const float*)d_in[1];
    const float* eo      = (const float*)d_in[2];
    const float* mask    = (const float*)d_in[3];
    const float* emb     = (const float*)d_in[4];
    const float* attn_W  = (const float*)d_in[5];
    const float* attn_b  = (const float*)d_in[6];
    const float* comb_W  = (const float*)d_in[7];
    const float* comb_b  = (const float*)d_in[8];
    const float* W_ih    = (const float*)d_in[9];
    const float* W_hh    = (const float*)d_in[10];
    const float* b_ih    = (const float*)d_in[11];
    const float* b_hh    = (const float*)d_in[12];
    const float* out_W   = (const float*)d_in[13];
    const float* out_b   = (const float*)d_in[14];

    float* out    = (float*)d_out;                       // [N, O]
    float* h_new  = out + (size_t)NB * OO;               // [N, H]
    float* attn_w = h_new + (size_t)NB * HH;             // [N, L]

    float* gxp;   cudaGetSymbolAddress((void**)&gxp,  g_gx);
    float* ghp;   cudaGetSymbolAddress((void**)&ghp,  g_gh);
    float* rsp;   cudaGetSymbolAddress((void**)&rsp,  g_rowsum);
    float* scrp;  cudaGetSymbolAddress((void**)&scrp, g_scr);
    __half *catp, *xp, *hidp, *hnp, *logp, *aWp, *cWp, *ihp, *hhp, *oWp;
    cudaGetSymbolAddress((void**)&catp, g_cat_h);
    cudaGetSymbolAddress((void**)&xp,   g_x_h);
    cudaGetSymbolAddress((void**)&hidp, g_hid_h);
    cudaGetSymbolAddress((void**)&hnp,  g_hnew_h);
    cudaGetSymbolAddress((void**)&logp, g_logit_h);
    cudaGetSymbolAddress((void**)&aWp,  g_attnW_h);
    cudaGetSymbolAddress((void**)&cWp,  g_combW_h);
    cudaGetSymbolAddress((void**)&ihp,  g_Wih_h);
    cudaGetSymbolAddress((void**)&hhp,  g_Whh_h);
    cudaGetSymbolAddress((void**)&oWp,  g_outW_h);

    const int SMEM = 3 * HSTAGE * sizeof(__half);        // 61440 B
    cudaFuncSetAttribute(k_gemm_f16, cudaFuncAttributeMaxDynamicSharedMemorySize, SMEM);
    cudaFuncSetAttribute(k_out_h, cudaFuncAttributeMaxDynamicSharedMemorySize, SMEM);

    // one-time side stream + fork/join events (host resources only)
    static cudaStream_t s2 = nullptr;
    static cudaEvent_t  e0 = nullptr, e1 = nullptr, eW = nullptr,
                        eC = nullptr, eG = nullptr, e3 = nullptr;
    if (!s2) {
        cudaStreamCreateWithFlags(&s2, cudaStreamNonBlocking);
        cudaEventCreateWithFlags(&e0, cudaEventDisableTiming);
        cudaEventCreateWithFlags(&e1, cudaEventDisableTiming);
        cudaEventCreateWithFlags(&eW, cudaEventDisableTiming);
        cudaEventCreateWithFlags(&eC, cudaEventDisableTiming);
        cudaEventCreateWithFlags(&eG, cudaEventDisableTiming);
        cudaEventCreateWithFlags(&e3, cudaEventDisableTiming);
    }

    // ---- fork ------------------------------------------------------------------
    cudaEventRecord(e0, 0);
    cudaStreamWaitEvent(s2, e0, 0);

    // main: build cat (hidden fp16 feeds gh on side stream)
    k_build_cat<<<NB, 128>>>(ids, hidden, emb);
    cudaEventRecord(eC, 0);

    // side: zero split-K accumulators + rowsum, then attn_W fp16
    k_zero_all<<<(Z_TOT + 255) / 256, 256, 0, s2>>>((float4*)attn_w);
    k_f2h<<<LL * H2 / 4 / 256, 256, 0, s2>>>((const float4*)attn_W,
                                             (__half2*)aWp, LL * H2 / 4);
    cudaEventRecord(e1, s2);
    // side: comb/ih/hh fp16
    k_f2h3<<<2048, 256, 0, s2>>>((const float4*)comb_W, (const float4*)W_ih,
                                 (const float4*)W_hh);
    cudaEventRecord(eW, s2);
    // side: gh = hidden @ W_hh^T + b_hh  (compute, overlaps DRAM-bound attn)
    cudaStreamWaitEvent(s2, eC, 0);
    {
        dim3 grid(H3 / 128, NB / 128, 1);
        k_gemm_f16<<<grid, 256, SMEM, s2>>>(hidp, hhp, b_hh, ghp, nullptr, nullptr,
                                            H3, HH, HH, 0);
    }
    cudaEventRecord(eG, s2);
    // side: out_W fp16 (only needed by big GEMM)
    k_f2h<<<(OO * HH / 4) / 256, 256, 0, s2>>>((const float4*)out_W,
                                               (__half2*)oWp, OO * HH / 4);
    cudaEventRecord(e3, s2);

    // ---- main chain --------------------------------------------------------------
    cudaStreamWaitEvent(0, e1, 0);
    // 2. attn logits, split-K=4, atomic (bias folded into fused softmax)
    {
        dim3 grid(LL / 128, NB / 128, 4);
        k_gemm_f16<<<grid, 256, SMEM>>>(catp, aWp, nullptr, attn_w, nullptr, nullptr,
                                        LL, H2, H2 / 4, 3);
    }
    // 3+4. fused softmax + attn_applied
    k_attn_smax_apply<<<NB, 128>>>(eo, mask, attn_w, attn_b);

    cudaStreamWaitEvent(0, eW, 0);
    // 5. comb split-K=4 atomic -> scr, then relu+bias -> fp16 x
    {
        dim3 grid(HH / 128, NB / 128, 4);
        k_gemm_f16<<<grid, 256, SMEM>>>(catp, cWp, nullptr, scrp, nullptr, nullptr,
                                        HH, H2, H2 / 4, 3);
    }
    k_relu_bias<<<NB * HH / 2 / 256, 256>>>(comb_b);
    // 6. gx split-K=2 atomic (b_ih added in k_gru)
    {
        dim3 grid(H3 / 128, NB / 128, 2);
        k_gemm_f16<<<grid, 256, SMEM>>>(xp, ihp, nullptr, gxp, nullptr, nullptr,
                                        H3, HH, HH / 2, 3);
    }
    cudaStreamWaitEvent(0, eG, 0);                 // gh done (side stream)
    // 8. GRU gates -> h_new
    k_gru<<<(NB * HH + 255) / 256, 256>>>(hidden, b_ih, h_new);

    cudaStreamWaitEvent(0, e3, 0);                 // out_W fp16 ready
    // 9. big output GEMM with fp16 accumulators -> fp16 logits + exp-sum
    {
        dim3 grid(OO / 128, NB / 128, 1);
        k_out_h<<<grid, 256, SMEM>>>(hnp, oWp, out_b, logp, rsp);
    }
    // 10. finalize log-softmax: out = fp16_logit - lse (fp32)
    k_sub_lse<<<NB, 256>>>(out);
}

// round 15
// speedup vs baseline: 1.0728x; 1.0673x over previous
#include <cuda_runtime.h>
#include <cuda_fp16.h>
#include <math.h>
#include <stdint.h>

// Problem dims
#define NB   1024
#define LL   128
#define HH   512
#define OO   32000
#define H2   1024   // 2H
#define H3   1536   // 3H

#define HPAD  40    // smem row stride (halfs) for BK=32 kernel
#define HPAD2 72    // smem row stride (halfs) for BK=64 kernel

// ---------------- scratch (device globals; no allocation allowed) -----------
__device__ __align__(16) __half g_cat_h [NB * H2];
__device__ __align__(16) __half g_x_h   [NB * HH];
__device__ __align__(16) __half g_hid_h [NB * HH];
__device__ __align__(16) __half g_hnew_h[NB * HH];
__device__ __align__(16) __half g_logit_h[NB * OO];  // fp16 logits (65.5 MB)
__device__ __align__(16) float g_scr [NB * HH];      // comb split-K accumulator
__device__ __align__(16) float g_gx [NB * H3];
__device__ __align__(16) float g_gh [NB * H3];
__device__ __align__(16) float g_rowsum[NB];

// fp16 weight copies
__device__ __align__(16) __half g_attnW_h[LL * H2];
__device__ __align__(16) __half g_combW_h[HH * H2];
__device__ __align__(16) __half g_Wih_h  [H3 * HH];
__device__ __align__(16) __half g_Whh_h  [H3 * HH];
__device__ __align__(16) __half g_outW_h [OO * HH];

// ---------------- PTX helpers ------------------------------------------------
__device__ __forceinline__ uint32_t smem_u32(const void* p)
{
    return (uint32_t)__cvta_generic_to_shared(p);
}
__device__ __forceinline__ void cpasync16(uint32_t s, const void* g)
{
    asm volatile("cp.async.cg.shared.global [%0], [%1], 16;\n" :: "r"(s), "l"(g));
}
__device__ __forceinline__ void cp_commit() { asm volatile("cp.async.commit_group;\n"); }
__device__ __forceinline__ void cp_wait1()  { asm volatile("cp.async.wait_group 1;\n"); }

__device__ __forceinline__ void ldsm_x4(uint32_t* r, uint32_t addr)
{
    asm volatile("ldmatrix.sync.aligned.m8n8.x4.shared.b16 {%0,%1,%2,%3}, [%4];\n"
                 : "=r"(r[0]), "=r"(r[1]), "=r"(r[2]), "=r"(r[3]) : "r"(addr));
}
__device__ __forceinline__ void ldsm_x2(uint32_t* r, uint32_t addr)
{
    asm volatile("ldmatrix.sync.aligned.m8n8.x2.shared.b16 {%0,%1}, [%2];\n"
                 : "=r"(r[0]), "=r"(r[1]) : "r"(addr));
}
__device__ __forceinline__ void mma_f16(float* d, const uint32_t* a, const uint32_t* b)
{
    asm volatile(
        "mma.sync.aligned.m16n8k16.row.col.f32.f16.f16.f32 "
        "{%0,%1,%2,%3}, {%4,%5,%6,%7}, {%8,%9}, {%0,%1,%2,%3};\n"
        : "+f"(d[0]), "+f"(d[1]), "+f"(d[2]), "+f"(d[3])
        : "r"(a[0]), "r"(a[1]), "r"(a[2]), "r"(a[3]), "r"(b[0]), "r"(b[1]));
}

// =============================================================================
// fp16 HMMA GEMM (proven mainloop): BM=BN=128, BK=32, 256 thr, 64x32 warps.
// Split-K via blockIdx.z (koff = z*Ksub).
// mode 0: fp32 C+bias. mode 1: relu -> fp16 Ch.
// mode 2: fp16 logits -> Ch (+bias) + fp32 exp-sum into rowsum.
// mode 3: atomicAdd fp32 C, no bias.
// =============================================================================
#define HSTAGE (2 * 128 * HPAD)

__global__ __launch_bounds__(256, 2)
void k_gemm_f16(const __half* __restrict__ A, const __half* __restrict__ W,
                const float* __restrict__ bias,
                float* __restrict__ C, __half* __restrict__ Ch,
                float* __restrict__ rowsum,
                int Nd, int Kstride, int Ksub, int mode)
{
    extern __shared__ __half smh[];

    const int bm   = blockIdx.y * 128;
    const int bn   = blockIdx.x * 128;
    const int koff = blockIdx.z * Ksub;
    const int tid  = threadIdx.x;
    const int warp = tid >> 5;
    const int lane = tid & 31;
    const int gid  = lane >> 2;
    const int tig  = lane & 3;
    const int wm   = (warp >> 2) * 64;
    const int wn   = (warp & 3) * 32;

    const int arow = wm + (lane & 15);
    const int acol = (lane >> 4) * 8;
    const int brow = wn + (lane & 7);
    const int bcol = ((lane >> 3) & 1) * 8;

    const uint32_t smem_b = smem_u32(smh);

    float acc[4][4][4];
    #pragma unroll
    for (int i = 0; i < 4; i++)
        #pragma unroll
        for (int j = 0; j < 4; j++)
            #pragma unroll
            for (int r = 0; r < 4; r++) acc[i][j][r] = 0.f;

    const __half* Ag = A + (size_t)bm * Kstride + koff;
    const __half* Wg = W + (size_t)bn * Kstride + koff;
    const int nIter = Ksub >> 5;

    auto load_tiles = [&](int it, int stg) {
        const __half* a_src = Ag + it * 32;
        const __half* w_src = Wg + it * 32;
        uint32_t aBase = smem_b + (stg * HSTAGE) * 2u;
        uint32_t bBase = aBase + 128 * HPAD * 2u;
        #pragma unroll
        for (int j = 0; j < 2; j++) {
            int idx = tid + j * 256;
            int r = idx >> 2;
            int c = (idx & 3) * 8;
            cpasync16(aBase + (r * HPAD + c) * 2u, a_src + (size_t)r * Kstride + c);
        }
        #pragma unroll
        for (int j = 0; j < 2; j++) {
            int idx = tid + j * 256;
            int r = idx >> 2;
            int c = (idx & 3) * 8;
            cpasync16(bBase + (r * HPAD + c) * 2u, w_src + (size_t)r * Kstride + c);
        }
    };

    load_tiles(0, 0); cp_commit();
    load_tiles(1, 1); cp_commit();

    int stg = 0;
    for (int it = 0; it < nIter; ++it) {
        cp_wait1();
        __syncthreads();

        if (it + 2 < nIter) load_tiles(it + 2, (stg + 2) % 3);
        cp_commit();

        const uint32_t aBase = smem_b + (stg * HSTAGE) * 2u;
        const uint32_t bBase = aBase + 128 * HPAD * 2u;

        #pragma unroll
        for (int kk = 0; kk < 2; kk++) {
            uint32_t af[4][4], bf[4][2];
            #pragma unroll
            for (int mt = 0; mt < 4; mt++)
                ldsm_x4(af[mt], aBase + (((arow + mt * 16) * HPAD) + kk * 16 + acol) * 2u);
            #pragma unroll
            for (int nt = 0; nt < 4; nt++)
                ldsm_x2(bf[nt], bBase + (((brow + nt * 8) * HPAD) + kk * 16 + bcol) * 2u);
            #pragma unroll
            for (int mt = 0; mt < 4; mt++)
                #pragma unroll
                for (int nt = 0; nt < 4; nt++)
                    mma_f16(acc[mt][nt], af[mt], bf[nt]);
        }
        stg = (stg + 1) % 3;
    }

    #pragma unroll
    for (int mt = 0; mt < 4; mt++) {
        int r0 = bm + wm + mt * 16 + gid;
        float sum_lo = 0.f, sum_hi = 0.f;
        #pragma unroll
        for (int nt = 0; nt < 4; nt++) {
            int c0 = bn + wn + nt * 8 + tig * 2;
            if (mode == 3) {
                atomicAdd(&C[(size_t)(r0    ) * Nd + c0],     acc[mt][nt][0]);
                atomicAdd(&C[(size_t)(r0    ) * Nd + c0 + 1], acc[mt][nt][1]);
                atomicAdd(&C[(size_t)(r0 + 8) * Nd + c0],     acc[mt][nt][2]);
                atomicAdd(&C[(size_t)(r0 + 8) * Nd + c0 + 1], acc[mt][nt][3]);
                continue;
            }
            float b0v = bias[c0], b1v = bias[c0 + 1];
            float v0 = acc[mt][nt][0] + b0v;
            float v1 = acc[mt][nt][1] + b1v;
            float v2 = acc[mt][nt][2] + b0v;
            float v3 = acc[mt][nt][3] + b1v;
            if (mode == 1) {
                v0 = fmaxf(v0, 0.f); v1 = fmaxf(v1, 0.f);
                v2 = fmaxf(v2, 0.f); v3 = fmaxf(v3, 0.f);
                *(__half2*)&Ch[(size_t)(r0    ) * Nd + c0] = __floats2half2_rn(v0, v1);
                *(__half2*)&Ch[(size_t)(r0 + 8) * Nd + c0] = __floats2half2_rn(v2, v3);
            } else if (mode == 2) {
                sum_lo += __expf(v0) + __expf(v1);
                sum_hi += __expf(v2) + __expf(v3);
                *(__half2*)&Ch[(size_t)(r0    ) * Nd + c0] = __floats2half2_rn(v0, v1);
                *(__half2*)&Ch[(size_t)(r0 + 8) * Nd + c0] = __floats2half2_rn(v2, v3);
            } else {
                *(float2*)&C[(size_t)(r0    ) * Nd + c0] = make_float2(v0, v1);
                *(float2*)&C[(size_t)(r0 + 8) * Nd + c0] = make_float2(v2, v3);
            }
        }
        if (mode == 2) {
            sum_lo += __shfl_xor_sync(0xffffffff, sum_lo, 1);
            sum_lo += __shfl_xor_sync(0xffffffff, sum_lo, 2);
            sum_hi += __shfl_xor_sync(0xffffffff, sum_hi, 1);
            sum_hi += __shfl_xor_sync(0xffffffff, sum_hi, 2);
            if (tig == 0) {
                atomicAdd(&rowsum[r0],     sum_lo);
                atomicAdd(&rowsum[r0 + 8], sum_hi);
            }
        }
    }
}

// =============================================================================
// Big output GEMM, BK=64 (halved iteration count): fp32 acc, fused bias +
// exp-sum + fp16 logit store. 3-stage cp.async, 110.6 KB smem, 2 CTA/SM.
// =============================================================================
#define HSTAGE2 (2 * 128 * HPAD2)

__global__ __launch_bounds__(256, 2)
void k_out2(const __half* __restrict__ A, const __half* __restrict__ W,
            const float* __restrict__ bias, __half* __restrict__ Ch,
            float* __restrict__ rowsum)
{
    extern __shared__ __half smh[];

    const int bm   = blockIdx.y * 128;
    const int bn   = blockIdx.x * 128;
    const int tid  = threadIdx.x;
    const int warp = tid >> 5;
    const int lane = tid & 31;
    const int gid  = lane >> 2;
    const int tig  = lane & 3;
    const int wm   = (warp >> 2) * 64;
    const int wn   = (warp & 3) * 32;

    const int arow = wm + (lane & 15);
    const int acol = (lane >> 4) * 8;
    const int brow = wn + (lane & 7);
    const int bcol = ((lane >> 3) & 1) * 8;

    const uint32_t smem_b = smem_u32(smh);

    float acc[4][4][4];
    #pragma unroll
    for (int i = 0; i < 4; i++)
        #pragma unroll
        for (int j = 0; j < 4; j++)
            #pragma unroll
            for (int r = 0; r < 4; r++) acc[i][j][r] = 0.f;

    const __half* Ag = A + (size_t)bm * HH;
    const __half* Wg = W + (size_t)bn * HH;
    const int nIter = HH >> 6;     // 8 iterations of BK=64

    // per stage: A 128x64 halfs + B 128x64 halfs; 64 halfs = 8 x 16B chunks/row
    auto load_tiles = [&](int it, int stg) {
        const __half* a_src = Ag + it * 64;
        const __half* w_src = Wg + it * 64;
        uint32_t aBase = smem_b + (stg * HSTAGE2) * 2u;
        uint32_t bBase = aBase + 128 * HPAD2 * 2u;
        #pragma unroll
        for (int j = 0; j < 4; j++) {
            int idx = tid + j * 256;         // 0..1023
            int r = idx >> 3;
            int c = (idx & 7) * 8;
            cpasync16(aBase + (r * HPAD2 + c) * 2u, a_src + (size_t)r * HH + c);
        }
        #pragma unroll
        for (int j = 0; j < 4; j++) {
            int idx = tid + j * 256;
            int r = idx >> 3;
            int c = (idx & 7) * 8;
            cpasync16(bBase + (r * HPAD2 + c) * 2u, w_src + (size_t)r * HH + c);
        }
    };

    load_tiles(0, 0); cp_commit();
    load_tiles(1, 1); cp_commit();

    int stg = 0;
    for (int it = 0; it < nIter; ++it) {
        cp_wait1();
        __syncthreads();

        if (it + 2 < nIter) load_tiles(it + 2, (stg + 2) % 3);
        cp_commit();

        const uint32_t aBase = smem_b + (stg * HSTAGE2) * 2u;
        const uint32_t bBase = aBase + 128 * HPAD2 * 2u;

        #pragma unroll
        for (int kk = 0; kk < 4; kk++) {
            uint32_t af[4][4], bf[4][2];
            #pragma unroll
            for (int mt = 0; mt < 4; mt++)
                ldsm_x4(af[mt], aBase + (((arow + mt * 16) * HPAD2) + kk * 16 + acol) * 2u);
            #pragma unroll
            for (int nt = 0; nt < 4; nt++)
                ldsm_x2(bf[nt], bBase + (((brow + nt * 8) * HPAD2) + kk * 16 + bcol) * 2u);
            #pragma unroll
            for (int mt = 0; mt < 4; mt++)
                #pragma unroll
                for (int nt = 0; nt < 4; nt++)
                    mma_f16(acc[mt][nt], af[mt], bf[nt]);
        }
        stg = (stg + 1) % 3;
    }

    // epilogue: bias + exp-sum + fp16 logit store
    #pragma unroll
    for (int mt = 0; mt < 4; mt++) {
        int r0 = bm + wm + mt * 16 + gid;
        float sum_lo = 0.f, sum_hi = 0.f;
        #pragma unroll
        for (int nt = 0; nt < 4; nt++) {
            int c0 = bn + wn + nt * 8 + tig * 2;
            float b0v = bias[c0], b1v = bias[c0 + 1];
            float v0 = acc[mt][nt][0] + b0v;
            float v1 = acc[mt][nt][1] + b1v;
            float v2 = acc[mt][nt][2] + b0v;
            float v3 = acc[mt][nt][3] + b1v;
            sum_lo += __expf(v0) + __expf(v1);
            sum_hi += __expf(v2) + __expf(v3);
            *(__half2*)&Ch[(size_t)(r0    ) * OO + c0] = __floats2half2_rn(v0, v1);
            *(__half2*)&Ch[(size_t)(r0 + 8) * OO + c0] = __floats2half2_rn(v2, v3);
        }
        sum_lo += __shfl_xor_sync(0xffffffff, sum_lo, 1);
        sum_lo += __shfl_xor_sync(0xffffffff, sum_lo, 2);
        sum_hi += __shfl_xor_sync(0xffffffff, sum_hi, 1);
        sum_hi += __shfl_xor_sync(0xffffffff, sum_hi, 2);
        if (tig == 0) {
            atomicAdd(&rowsum[r0],     sum_lo);
            atomicAdd(&rowsum[r0 + 8], sum_hi);
        }
    }
}

// ---------------- fp32 -> fp16 conversion -------------------------------------
__device__ __forceinline__ void f2h_one(const float4* __restrict__ s,
                                        __half2* __restrict__ d, int i)
{
    float4 v = s[i];
    d[2 * i]     = __floats2half2_rn(v.x, v.y);
    d[2 * i + 1] = __floats2half2_rn(v.z, v.w);
}

__global__ void k_f2h(const float4* __restrict__ src, __half2* __restrict__ dst, int n4)
{
    int i = blockIdx.x * blockDim.x + threadIdx.x;
    if (i < n4) f2h_one(src, dst, i);
}

__global__ void k_f2h3(const float4* __restrict__ combW,
                       const float4* __restrict__ Wih,
                       const float4* __restrict__ Whh)
{
    const int b = blockIdx.x;
    const int t = threadIdx.x;
    if (b < 512) {
        f2h_one(combW, (__half2*)g_combW_h, b * 256 + t);
    } else if (b < 1280) {
        f2h_one(Wih, (__half2*)g_Wih_h, (b - 512) * 256 + t);
    } else {
        f2h_one(Whh, (__half2*)g_Whh_h, (b - 1280) * 256 + t);
    }
}

// ---------------- zero all split-K accumulators + rowsum ----------------------
#define Z_ATTN  32768
#define Z_SCR   (Z_ATTN + 131072)
#define Z_GX    (Z_SCR + 393216)
#define Z_TOT   (Z_GX + 256)

__global__ void k_zero_all(float4* __restrict__ attn_w)
{
    int i = blockIdx.x * 256 + threadIdx.x;
    float4 z = make_float4(0.f, 0.f, 0.f, 0.f);
    if (i < Z_ATTN)      attn_w[i] = z;
    else if (i < Z_SCR)  ((float4*)g_scr)[i - Z_ATTN] = z;
    else if (i < Z_GX)   ((float4*)g_gx)[i - Z_SCR] = z;
    else if (i < Z_TOT)  ((float4*)g_rowsum)[i - Z_GX] = z;
}

// ---------------- K1: cat = [emb[id] | hidden] (fp16) + hidden fp16 ----------
__global__ void k_build_cat(const int* __restrict__ ids,
                            const float* __restrict__ hidden,
                            const float* __restrict__ emb)
{
    int n = blockIdx.x;
    int id = ids[n];
    int i = threadIdx.x;                  // 128 threads
    float4 e = ((const float4*)(emb    + (size_t)id * HH))[i];
    float4 h = ((const float4*)(hidden + (size_t)n  * HH))[i];

    __half2* c = (__half2*)(g_cat_h + (size_t)n * H2);
    c[2 * i]           = __floats2half2_rn(e.x, e.y);
    c[2 * i + 1]       = __floats2half2_rn(e.z, e.w);
    c[256 + 2 * i]     = __floats2half2_rn(h.x, h.y);
    c[256 + 2 * i + 1] = __floats2half2_rn(h.z, h.w);

    __half2* hh = (__half2*)(g_hid_h + (size_t)n * HH);
    hh[2 * i]     = __floats2half2_rn(h.x, h.y);
    hh[2 * i + 1] = __floats2half2_rn(h.z, h.w);
}

// ---------------- fused: softmax(logits + bias) + attn einsum ----------------
__global__ void k_attn_smax_apply(const float* __restrict__ eo,
                                  const float* __restrict__ mask,
                                  float* __restrict__ attn_w,
                                  const float* __restrict__ ab)
{
    __shared__ float red[128];
    __shared__ float ws[LL];
    int n = blockIdx.x;
    int t = threadIdx.x;                  // 128 threads

    float v = attn_w[(size_t)n * LL + t] + ab[t];

    red[t] = v; __syncthreads();
    for (int s = 64; s > 0; s >>= 1) {
        if (t < s) red[t] = fmaxf(red[t], red[t + s]);
        __syncthreads();
    }
    float m = red[0]; __syncthreads();

    float e = expf(v - m);
    red[t] = e; __syncthreads();
    for (int s = 64; s > 0; s >>= 1) {
        if (t < s) red[t] += red[t + s];
        __syncthreads();
    }
    float w = e / red[0];
    attn_w[(size_t)n * LL + t] = w;       // final attn weights (harness output)
    ws[t] = w;
    __syncthreads();

    const float4* e4 = (const float4*)(eo   + (size_t)n * LL * HH) + t;
    const float4* m4 = (const float4*)(mask + (size_t)n * LL * HH) + t;

    float4 acc = make_float4(0.f, 0.f, 0.f, 0.f);
    #pragma unroll 4
    for (int l = 0; l < LL; l++) {
        float4 e = e4[(size_t)l * 128];
        float4 m = m4[(size_t)l * 128];
        float  wv = ws[l];
        acc.x = fmaf(wv, e.x * m.x, acc.x);
        acc.y = fmaf(wv, e.y * m.y, acc.y);
        acc.z = fmaf(wv, e.z * m.z, acc.z);
        acc.w = fmaf(wv, e.w * m.w, acc.w);
    }
    __half2* dst = (__half2*)(g_cat_h + (size_t)n * H2 + HH);
    dst[2 * t]     = __floats2half2_rn(acc.x, acc.y);
    dst[2 * t + 1] = __floats2half2_rn(acc.z, acc.w);
}

// ---------------- relu(scr + comb_b) -> fp16 x --------------------------------
__global__ void k_relu_bias(const float* __restrict__ cb)
{
    int i = blockIdx.x * blockDim.x + threadIdx.x;    // over NB*HH/2
    int i2 = 2 * i;
    int c = i2 & (HH - 1);
    float v0 = fmaxf(g_scr[i2]     + cb[c],     0.f);
    float v1 = fmaxf(g_scr[i2 + 1] + cb[c + 1], 0.f);
    ((__half2*)g_x_h)[i] = __floats2half2_rn(v0, v1);
}

// ---------------- GRU gates (adds b_ih to gx) ---------------------------------
__global__ void k_gru(const float* __restrict__ hidden,
                      const float* __restrict__ b_ih,
                      float* __restrict__ h_new)
{
    int idx = blockIdx.x * blockDim.x + threadIdx.x;
    if (idx >= NB * HH) return;
    int n = idx >> 9;
    int h = idx & (HH - 1);
    size_t base = (size_t)n * H3 + h;

    float xr = g_gx[base]          + b_ih[h];
    float xz = g_gx[base + HH]     + b_ih[h + HH];
    float xn = g_gx[base + 2 * HH] + b_ih[h + 2 * HH];
    float hr = g_gh[base], hz = g_gh[base + HH], hn = g_gh[base + 2 * HH];

    float r = 1.f / (1.f + expf(-(xr + hr)));
    float z = 1.f / (1.f + expf(-(xz + hz)));
    float nn = tanhf(xn + r * hn);
    float hv = (1.f - z) * nn + z * hidden[idx];
    h_new[idx] = hv;
    g_hnew_h[idx] = __float2half_rn(hv);
}

// ---------------- out = fp16_logit - log(rowsum) (fp32 write) ------------------
__global__ void k_sub_lse(float* __restrict__ x)
{
    int n = blockIdx.x;
    float lse = __logf(g_rowsum[n]);
    const uint2* src = (const uint2*)(g_logit_h + (size_t)n * OO);
    float4* dst = (float4*)(x + (size_t)n * OO);
    for (int i = threadIdx.x; i < OO / 4; i += blockDim.x) {
        uint2 u = src[i];
        float2 a = __half22float2(*(__half2*)&u.x);
        float2 b = __half22float2(*(__half2*)&u.y);
        dst[i] = make_float4(a.x - lse, a.y - lse, b.x - lse, b.y - lse);
    }
}

// ---------------- launch ---------------------------------------------------------
extern "C" void kernel_launch(void* const* d_in, const int* in_sizes, int n_in,
                              void* d_out, int out_size)
{
    const int*   ids     = (const int*)  d_in[0];
    const float* hidden  = (const float*)d_in[1];
    const float* eo      = (const float*)d_in[2];
    const float* mask    = (const float*)d_in[3];
    const float* emb     = (const float*)d_in[4];
    const float* attn_W  = (const float*)d_in[5];
    const float* attn_b  = (const float*)d_in[6];
    const float* comb_W  = (const float*)d_in[7];
    const float* comb_b  = (const float*)d_in[8];
    const float* W_ih    = (const float*)d_in[9];
    const float* W_hh    = (const float*)d_in[10];
    const float* b_ih    = (const float*)d_in[11];
    const float* b_hh    = (const float*)d_in[12];
    const float* out_W   = (const float*)d_in[13];
    const float* out_b   = (const float*)d_in[14];

    float* out    = (float*)d_out;                       // [N, O]
    float* h_new  = out + (size_t)NB * OO;               // [N, H]
    float* attn_w = h_new + (size_t)NB * HH;             // [N, L]

    float* gxp;   cudaGetSymbolAddress((void**)&gxp,  g_gx);
    float* ghp;   cudaGetSymbolAddress((void**)&ghp,  g_gh);
    float* rsp;   cudaGetSymbolAddress((void**)&rsp,  g_rowsum);
    float* scrp;  cudaGetSymbolAddress((void**)&scrp, g_scr);
    __half *catp, *xp, *hidp, *hnp, *logp, *aWp, *cWp, *ihp, *hhp, *oWp;
    cudaGetSymbolAddress((void**)&catp, g_cat_h);
    cudaGetSymbolAddress((void**)&xp,   g_x_h);
    cudaGetSymbolAddress((void**)&hidp, g_hid_h);
    cudaGetSymbolAddress((void**)&hnp,  g_hnew_h);
    cudaGetSymbolAddress((void**)&logp, g_logit_h);
    cudaGetSymbolAddress((void**)&aWp,  g_attnW_h);
    cudaGetSymbolAddress((void**)&cWp,  g_combW_h);
    cudaGetSymbolAddress((void**)&ihp,  g_Wih_h);
    cudaGetSymbolAddress((void**)&hhp,  g_Whh_h);
    cudaGetSymbolAddress((void**)&oWp,  g_outW_h);

    const int SMEM  = 3 * HSTAGE  * sizeof(__half);      // 61440 B
    const int SMEM2 = 3 * HSTAGE2 * sizeof(__half);      // 110592 B
    cudaFuncSetAttribute(k_gemm_f16, cudaFuncAttributeMaxDynamicSharedMemorySize, SMEM);
    cudaFuncSetAttribute(k_out2, cudaFuncAttributeMaxDynamicSharedMemorySize, SMEM2);

    // one-time side stream + fork/join events (host resources only)
    static cudaStream_t s2 = nullptr;
    static cudaEvent_t  e0 = nullptr, e1 = nullptr, eW = nullptr,
                        eC = nullptr, eG = nullptr, e3 = nullptr;
    if (!s2) {
        cudaStreamCreateWithFlags(&s2, cudaStreamNonBlocking);
        cudaEventCreateWithFlags(&e0, cudaEventDisableTiming);
        cudaEventCreateWithFlags(&e1, cudaEventDisableTiming);
        cudaEventCreateWithFlags(&eW, cudaEventDisableTiming);
        cudaEventCreateWithFlags(&eC, cudaEventDisableTiming);
        cudaEventCreateWithFlags(&eG, cudaEventDisableTiming);
        cudaEventCreateWithFlags(&e3, cudaEventDisableTiming);
    }

    // ---- fork ------------------------------------------------------------------
    cudaEventRecord(e0, 0);
    cudaStreamWaitEvent(s2, e0, 0);

    // main: build cat (hidden fp16 feeds gh on side stream)
    k_build_cat<<<NB, 128>>>(ids, hidden, emb);
    cudaEventRecord(eC, 0);

    // side: zero split-K accumulators + rowsum, then attn_W fp16
    k_zero_all<<<(Z_TOT + 255) / 256, 256, 0, s2>>>((float4*)attn_w);
    k_f2h<<<LL * H2 / 4 / 256, 256, 0, s2>>>((const float4*)attn_W,
                                             (__half2*)aWp, LL * H2 / 4);
    cudaEventRecord(e1, s2);
    // side: comb/ih/hh fp16
    k_f2h3<<<2048, 256, 0, s2>>>((const float4*)comb_W, (const float4*)W_ih,
                                 (const float4*)W_hh);
    cudaEventRecord(eW, s2);
    // side: gh = hidden @ W_hh^T + b_hh  (compute, overlaps DRAM-bound attn)
    cudaStreamWaitEvent(s2, eC, 0);
    {
        dim3 grid(H3 / 128, NB / 128, 1);
        k_gemm_f16<<<grid, 256, SMEM, s2>>>(hidp, hhp, b_hh, ghp, nullptr, nullptr,
                                            H3, HH, HH, 0);
    }
    cudaEventRecord(eG, s2);
    // side: out_W fp16 (only needed by big GEMM)
    k_f2h<<<(OO * HH / 4) / 256, 256, 0, s2>>>((const float4*)out_W,
                                               (__half2*)oWp, OO * HH / 4);
    cudaEventRecord(e3, s2);

    // ---- main chain --------------------------------------------------------------
    cudaStreamWaitEvent(0, e1, 0);
    // 2. attn logits, split-K=4, atomic (bias folded into fused softmax)
    {
        dim3 grid(LL / 128, NB / 128, 4);
        k_gemm_f16<<<grid, 256, SMEM>>>(catp, aWp, nullptr, attn_w, nullptr, nullptr,
                                        LL, H2, H2 / 4, 3);
    }
    // 3+4. fused softmax + attn_applied
    k_attn_smax_apply<<<NB, 128>>>(eo, mask, attn_w, attn_b);

    cudaStreamWaitEvent(0, eW, 0);
    // 5. comb split-K=4 atomic -> scr, then relu+bias -> fp16 x
    {
        dim3 grid(HH / 128, NB / 128, 4);
        k_gemm_f16<<<grid, 256, SMEM>>>(catp, cWp, nullptr, scrp, nullptr, nullptr,
                                        HH, H2, H2 / 4, 3);
    }
    k_relu_bias<<<NB * HH / 2 / 256, 256>>>(comb_b);
    // 6. gx split-K=2 atomic (b_ih added in k_gru)
    {
        dim3 grid(H3 / 128, NB / 128, 2);
        k_gemm_f16<<<grid, 256, SMEM>>>(xp, ihp, nullptr, gxp, nullptr, nullptr,
                                        H3, HH, HH / 2, 3);
    }
    cudaStreamWaitEvent(0, eG, 0);                 // gh done (side stream)
    // 8. GRU gates -> h_new
    k_gru<<<(NB * HH + 255) / 256, 256>>>(hidden, b_ih, h_new);

    cudaStreamWaitEvent(0, e3, 0);                 // out_W fp16 ready
    // 9. big output GEMM, BK=64, fp32 acc -> fp16 logits + exp-sum
    {
        dim3 grid(OO / 128, NB / 128, 1);
        k_out2<<<grid, 256, SMEM2>>>(hnp, oWp, out_b, logp, rsp);
    }
    // 10. finalize log-softmax: out = fp16_logit - lse (fp32)
    k_sub_lse<<<NB, 256>>>(out);
}